// round 14
// baseline (speedup 1.0000x reference)
#include <cuda_runtime.h>
#include <cuda_bf16.h>
#include <cstdint>

// Problem constants
#define NROWS   64000      // B*T
#define TT      1000
#define INS     257
#define KP      272        // padded K for gate GEMM
#define XSTR    544        // Xe row stride in bf16: [hi 272 | lo 272]
#define HID     40
#define NGATE   480
#define NGP     512        // padded N for gate GEMM
#define KEXP    720
#define OUTS    257
#define OUTN    256        // KAN GEMM covers cols 0..255; col 256 fused into feat

// gi smem (bf16 elems): per stage A 128x40, B 128x40
#define GA_E 5120
#define GI_STG 10240       // elems per stage (A+B)
// kan smem (f32 elems): per stage A 128x20, B 128x20
#define KA_E 2560
#define KAN_STG 5120       // floats per stage
#define SMEM_BYTES 81920   // 4 stages, both kernels (bytes)

// Static device scratch
__device__ __nv_bfloat16 g_Xe[(size_t)NROWS * XSTR];   // 69.6 MB
__device__ __nv_bfloat16 g_Wg[(size_t)NGP * XSTR];
__device__ float g_gi[(size_t)NROWS * NGATE];          // 122.9 MB
__device__ float g_E [(size_t)NROWS * KEXP];           // 184.3 MB (tf32-rounded)
__device__ float g_Wk[(size_t)OUTS * KEXP];            // tf32-rounded, 257 rows

__device__ __forceinline__ float sigf(float x) { return 1.0f / (1.0f + __expf(-x)); }
__device__ __forceinline__ unsigned tf32u(float v) {
    unsigned u; asm("cvt.rna.tf32.f32 %0, %1;" : "=r"(u) : "f"(v)); return u;
}
__device__ __forceinline__ float tf32f(float v) { return __uint_as_float(tf32u(v)); }

__device__ __forceinline__ void cp16(uint32_t dst, const void* src) {
    asm volatile("cp.async.cg.shared.global [%0], [%1], 16;" :: "r"(dst), "l"(src));
}
#define CP_COMMIT() asm volatile("cp.async.commit_group;")
#define CP_WAIT2()  asm volatile("cp.async.wait_group 2;")

#define MMAT(C, A, B) \
    asm volatile("mma.sync.aligned.m16n8k8.row.col.f32.tf32.tf32.f32 " \
        "{%0,%1,%2,%3},{%4,%5,%6,%7},{%8,%9},{%0,%1,%2,%3};" \
        : "+f"(C[0]), "+f"(C[1]), "+f"(C[2]), "+f"(C[3]) \
        : "r"(A[0]), "r"(A[1]), "r"(A[2]), "r"(A[3]), "r"(B[0]), "r"(B[1]))

#define MMAB(C, A, B) \
    asm volatile("mma.sync.aligned.m16n8k16.row.col.f32.bf16.bf16.f32 " \
        "{%0,%1,%2,%3},{%4,%5,%6,%7},{%8,%9},{%0,%1,%2,%3};" \
        : "+f"(C[0]), "+f"(C[1]), "+f"(C[2]), "+f"(C[3]) \
        : "r"(A[0]), "r"(A[1]), "r"(A[2]), "r"(A[3]), "r"(B[0]), "r"(B[1]))

// Cubic B-spline basis: grid[j] = 0.4*(j-3) - 1
__device__ __forceinline__ void bspline8(float x, float* o) {
    float bb[11];
#pragma unroll
    for (int j = 0; j < 11; j++) {
        float gA = 0.4f * (float)(j - 3) - 1.0f;
        float gB = 0.4f * (float)(j - 2) - 1.0f;
        bb[j] = (x >= gA && x < gB) ? 1.0f : 0.0f;
    }
#pragma unroll
    for (int k = 1; k <= 3; k++) {
        float inv = 1.0f / (0.4f * (float)k);
#pragma unroll
        for (int j = 0; j <= 10 - k; j++) {
            float gj = 0.4f * (float)(j - 3) - 1.0f;
            float gk = 0.4f * (float)(j + k - 2) - 1.0f;
            bb[j] = ((x - gj) * bb[j] + (gk - x) * bb[j + 1]) * inv;
        }
    }
#pragma unroll
    for (int m = 0; m < 8; m++) o[m] = bb[m];
}

// ---------------------------------------------------------------------------
// Prep: split X into bf16 hi|lo planes (4 elems/thread, 8B stores)
// ---------------------------------------------------------------------------
__global__ void prep_xe_kernel(const float* __restrict__ X) {
    int idx = blockIdx.x * 256 + threadIdx.x;   // over NROWS * 68
    if (idx >= NROWS * 68) return;
    int m = idx / 68, kp = (idx % 68) * 4;
    union { __nv_bfloat16 b[4]; uint2 u; } H, L;
#pragma unroll
    for (int j = 0; j < 4; j++) {
        int k = kp + j;
        float v = (k < INS) ? X[(size_t)m * INS + k] : 0.0f;
        __nv_bfloat16 hi = __float2bfloat16_rn(v);
        H.b[j] = hi;
        L.b[j] = __float2bfloat16_rn(v - __bfloat162float(hi));
    }
    *(uint2*)(g_Xe + (size_t)m * XSTR + kp)       = H.u;
    *(uint2*)(g_Xe + (size_t)m * XSTR + 272 + kp) = L.u;
}

// Prep: concat + split gate weights into bf16 hi|lo planes
__global__ void prep_wg_kernel(const float* __restrict__ Wf,
                               const float* __restrict__ Wb) {
    int idx = blockIdx.x * 256 + threadIdx.x;
    if (idx >= NGP * KP) return;
    int g = idx / KP, k = idx % KP;
    float v = 0.0f;
    if (g < NGATE && k < INS)
        v = (g < 240) ? Wf[(size_t)g * INS + k] : Wb[(size_t)(g - 240) * INS + k];
    __nv_bfloat16 hi = __float2bfloat16_rn(v);
    g_Wg[(size_t)g * XSTR + k]       = hi;
    g_Wg[(size_t)g * XSTR + 272 + k] = __float2bfloat16_rn(v - __bfloat162float(hi));
}

// Prep: tf32-rounded Wk = [base_weight | spline_weight*scaler], 257 full rows
__global__ void prep_wk_kernel(const float* __restrict__ base_w,
                               const float* __restrict__ spl_w,
                               const float* __restrict__ scaler) {
    int idx = blockIdx.x * 256 + threadIdx.x;
    if (idx >= OUTS * KEXP) return;
    int o = idx / KEXP, k = idx % KEXP;
    float v;
    if (k < 80) v = base_w[o * 80 + k];
    else {
        int q = k - 80;
        int i = q >> 3, m = q & 7;
        v = spl_w[(o * 80 + i) * 8 + m] * scaler[o * 80 + i];
    }
    g_Wk[idx] = tf32f(v);
}

// ---------------------------------------------------------------------------
// Kernel 1: gi = X * Wcat^T  (bf16 3-term, 128x128 block, term-major MMA order)
// ---------------------------------------------------------------------------
__global__ __launch_bounds__(128, 2)
void gemm_gi_kernel() {
    extern __shared__ __nv_bfloat16 smb[];
    const int tid = threadIdx.x, lane = tid & 31, w = tid >> 5;
    const int g = lane >> 2, c = lane & 3;
    const int wm = (w >> 1) * 64, wn = (w & 1) * 64;
    const int n0 = blockIdx.x * 128, m0 = blockIdx.y * 128;
    const uint32_t sb = (uint32_t)__cvta_generic_to_shared(smb);

    float acc[4][8][4];
#pragma unroll
    for (int i = 0; i < 4; i++)
#pragma unroll
        for (int j = 0; j < 8; j++)
#pragma unroll
            for (int l = 0; l < 4; l++) acc[i][j][l] = 0.0f;

    const int arow = tid >> 2, ach = tid & 3;
    const int asrc = (ach < 2) ? (ach * 8) : (272 + (ach - 2) * 8);
    const int adst = ach * 8;

    auto stage_copy = [&](int s, int t) {
        const int k0 = t * 16;
        const uint32_t abase = sb + (uint32_t)(s * GI_STG) * 2;
#pragma unroll
        for (int i = 0; i < 4; i++) {
            int row = arow + i * 32;
            cp16(abase + (uint32_t)(row * 40 + adst) * 2,
                 g_Xe + (size_t)(m0 + row) * XSTR + k0 + asrc);
        }
        const uint32_t bbase = abase + (uint32_t)GA_E * 2;
#pragma unroll
        for (int i = 0; i < 4; i++) {
            int row = arow + i * 32;
            cp16(bbase + (uint32_t)(row * 40 + adst) * 2,
                 g_Wg + (size_t)(n0 + row) * XSTR + k0 + asrc);
        }
    };

    const int NT = KP / 16;   // 17
#pragma unroll
    for (int s = 0; s < 3; s++) { stage_copy(s, s); CP_COMMIT(); }

    for (int t = 0; t < NT; t++) {
        CP_WAIT2();
        __syncthreads();
        if (t + 3 < NT) stage_copy((t + 3) & 3, t + 3);
        CP_COMMIT();

        const unsigned* Aw = (const unsigned*)(smb + (t & 3) * GI_STG);
        const unsigned* Bw = (const unsigned*)(smb + (t & 3) * GI_STG + GA_E);
        unsigned Ah[4][4], Al[4][4], bh[8][2], bl[8][2];
#pragma unroll
        for (int mt = 0; mt < 4; mt++) {
            const unsigned* p0 = Aw + (wm + mt * 16 + g) * 20;
            const unsigned* p1 = p0 + 8 * 20;
            Ah[mt][0] = p0[c];     Ah[mt][1] = p1[c];
            Ah[mt][2] = p0[c + 4]; Ah[mt][3] = p1[c + 4];
            Al[mt][0] = p0[8 + c];  Al[mt][1] = p1[8 + c];
            Al[mt][2] = p0[12 + c]; Al[mt][3] = p1[12 + c];
        }
#pragma unroll
        for (int nt = 0; nt < 8; nt++) {
            const unsigned* q = Bw + (wn + nt * 8 + g) * 20;
            bh[nt][0] = q[c];     bh[nt][1] = q[c + 4];
            bl[nt][0] = q[8 + c]; bl[nt][1] = q[12 + c];
        }
        // term-major: 32 independent MMAs per pass (no accumulator RAW chains)
#pragma unroll
        for (int nt = 0; nt < 8; nt++)
#pragma unroll
            for (int mt = 0; mt < 4; mt++)
                MMAB(acc[mt][nt], Ah[mt], bh[nt]);
#pragma unroll
        for (int nt = 0; nt < 8; nt++)
#pragma unroll
            for (int mt = 0; mt < 4; mt++)
                MMAB(acc[mt][nt], Al[mt], bh[nt]);
#pragma unroll
        for (int nt = 0; nt < 8; nt++)
#pragma unroll
            for (int mt = 0; mt < 4; mt++)
                MMAB(acc[mt][nt], Ah[mt], bl[nt]);
    }

#pragma unroll
    for (int mt = 0; mt < 4; mt++) {
        int r0 = m0 + wm + mt * 16 + g, r1 = r0 + 8;
#pragma unroll
        for (int nt = 0; nt < 8; nt++) {
            int o = n0 + wn + nt * 8 + 2 * c;
            if (o < NGATE) {
                float* C = acc[mt][nt];
                *(float2*)&g_gi[(size_t)r0 * NGATE + o] = make_float2(C[0], C[1]);
                *(float2*)&g_gi[(size_t)r1 * NGATE + o] = make_float2(C[2], C[3]);
            }
        }
    }
}

// ---------------------------------------------------------------------------
// Kernel 2: GRU cells + feature expansion + fused output column 256
// ---------------------------------------------------------------------------
__global__ __launch_bounds__(256)
void feat_kernel(const float* __restrict__ bih_f, const float* __restrict__ bhh_f,
                 const float* __restrict__ bih_b, const float* __restrict__ bhh_b,
                 const float* __restrict__ Whh_f, const float* __restrict__ Whh_b,
                 const float* __restrict__ slope, float* __restrict__ out) {
    __shared__ float sWf[40 * 120];
    __shared__ float sWb[40 * 120];
    __shared__ float sW256[KEXP];
    __shared__ float sh1f[4][40];
    __shared__ float sh1b[4][40];
    __shared__ float sred[4][2];

    const int tid = threadIdx.x, lane = tid & 31;
    for (int e = tid; e < 4800; e += 256) {
        int g = e / 40, j = e % 40;
        sWf[j * 120 + g] = Whh_f[4800 + e];
        sWb[j * 120 + g] = Whh_b[4800 + e];
    }
    for (int e = tid; e < KEXP; e += 256) sW256[e] = g_Wk[(size_t)256 * KEXP + e];
    __syncthreads();

    const int rl = tid >> 6;
    const int u  = tid & 63;
    const bool act = (u < HID);
    const float s256 = slope[256];

    float bf_r0=0, bf_z0=0, bf_n0=0, bb_r0=0, bb_z0=0, bb_n0=0;
    float if_r0=0, if_z0=0, if_n0=0, ib_r0=0, ib_z0=0, ib_n0=0;
    float bf_r1=0, bf_z1=0, bf_n1=0, bb_r1=0, bb_z1=0, bb_n1=0;
    float if_r1=0, if_z1=0, if_n1=0, ib_r1=0, ib_z1=0, ib_n1=0;
    if (act) {
        bf_r0 = bhh_f[u]; bf_z0 = bhh_f[40+u]; bf_n0 = bhh_f[80+u];
        bb_r0 = bhh_b[u]; bb_z0 = bhh_b[40+u]; bb_n0 = bhh_b[80+u];
        if_r0 = bih_f[u]; if_z0 = bih_f[40+u]; if_n0 = bih_f[80+u];
        ib_r0 = bih_b[u]; ib_z0 = bih_b[40+u]; ib_n0 = bih_b[80+u];
        bf_r1 = bhh_f[120+u]; bf_z1 = bhh_f[160+u]; bf_n1 = bhh_f[200+u];
        bb_r1 = bhh_b[120+u]; bb_z1 = bhh_b[160+u]; bb_n1 = bhh_b[200+u];
        if_r1 = bih_f[120+u]; if_z1 = bih_f[160+u]; if_n1 = bih_f[200+u];
        ib_r1 = bih_b[120+u]; ib_z1 = bih_b[160+u]; ib_n1 = bih_b[200+u];
    }

    for (int it = 0; it < 4; it++) {
        const int row = blockIdx.x * 16 + it * 4 + rl;
        const int b = row / TT, t = row % TT;
        const int row_rev = b * TT + (TT - 1 - t);
        const float* gf = g_gi + (size_t)row * NGATE;
        const float* gb = g_gi + (size_t)row_rev * NGATE;

        float h1f = 0.0f, h1b = 0.0f;
        if (act) {
            {
                float r = sigf(gf[u] + if_r0 + bf_r0);
                float z = sigf(gf[40 + u] + if_z0 + bf_z0);
                float n = tanhf(gf[80 + u] + if_n0 + r * bf_n0);
                h1f = (1.0f - z) * n;
                sh1f[rl][u] = h1f;
            }
            {
                float r = sigf(gb[240 + u] + ib_r0 + bb_r0);
                float z = sigf(gb[280 + u] + ib_z0 + bb_z0);
                float n = tanhf(gb[320 + u] + ib_n0 + r * bb_n0);
                h1b = (1.0f - z) * n;
                sh1b[rl][u] = h1b;
            }
        }
        __syncthreads();

        float part = 0.0f;
        if (act) {
            float gr = bf_r1, gz = bf_z1, gn = bf_n1;
#pragma unroll
            for (int j = 0; j < 40; j++) {
                float h = sh1f[rl][j];
                gr = fmaf(sWf[j * 120 + u],      h, gr);
                gz = fmaf(sWf[j * 120 + 40 + u], h, gz);
                gn = fmaf(sWf[j * 120 + 80 + u], h, gn);
            }
            float r = sigf(gf[120 + u] + if_r1 + gr);
            float z = sigf(gf[160 + u] + if_z1 + gz);
            float n = tanhf(gf[200 + u] + if_n1 + r * gn);
            float hf = (1.0f - z) * n + z * h1f;

            float br = bb_r1, bz = bb_z1, bn = bb_n1;
#pragma unroll
            for (int j = 0; j < 40; j++) {
                float h = sh1b[rl][j];
                br = fmaf(sWb[j * 120 + u],      h, br);
                bz = fmaf(sWb[j * 120 + 40 + u], h, bz);
                bn = fmaf(sWb[j * 120 + 80 + u], h, bn);
            }
            float r2 = sigf(gb[360 + u] + ib_r1 + br);
            float z2 = sigf(gb[400 + u] + ib_z1 + bz);
            float n2 = tanhf(gb[440 + u] + ib_n1 + r2 * bn);
            float hb = (1.0f - z2) * n2 + z2 * h1b;

            float* e = g_E + (size_t)row * KEXP;
            float e0 = tf32f(hf * sigf(hf));
            float e1 = tf32f(hb * sigf(hb));
            e[u]      = e0;
            e[40 + u] = e1;
            part = sW256[u] * e0 + sW256[40 + u] * e1;

            float bf[8], rv[8];
            bspline8(hf, bf);
#pragma unroll
            for (int j = 0; j < 8; j++) { rv[j] = tf32f(bf[j]); part = fmaf(sW256[80 + u * 8 + j], rv[j], part); }
            *(float4*)&e[80 + u * 8]     = make_float4(rv[0], rv[1], rv[2], rv[3]);
            *(float4*)&e[80 + u * 8 + 4] = make_float4(rv[4], rv[5], rv[6], rv[7]);

            bspline8(hb, bf);
#pragma unroll
            for (int j = 0; j < 8; j++) { rv[j] = tf32f(bf[j]); part = fmaf(sW256[80 + (40 + u) * 8 + j], rv[j], part); }
            *(float4*)&e[80 + (40 + u) * 8]     = make_float4(rv[0], rv[1], rv[2], rv[3]);
            *(float4*)&e[80 + (40 + u) * 8 + 4] = make_float4(rv[4], rv[5], rv[6], rv[7]);
        }

        // reduce col-256 partial across the 64-lane row group (2 warps)
        float tot = part;
#pragma unroll
        for (int off = 16; off; off >>= 1) tot += __shfl_xor_sync(0xffffffffu, tot, off);
        if (lane == 0) sred[rl][(tid >> 5) & 1] = tot;
        __syncthreads();
        if (u == 0)
            out[(size_t)row * OUTS + 256] = 1.2f * sigf(s256 * (sred[rl][0] + sred[rl][1]));
    }
}

// ---------------------------------------------------------------------------
// Kernel 3: out[:,0:256] = 1.2*sigmoid(slope*(E*Wk^T))  (tf32, 128x128, 2 CTA/SM)
// ---------------------------------------------------------------------------
__global__ __launch_bounds__(128, 2)
void gemm_kan_kernel(const float* __restrict__ slope, float* __restrict__ out) {
    extern __shared__ float smf[];
    const int tid = threadIdx.x, lane = tid & 31, w = tid >> 5;
    const int g = lane >> 2, c = lane & 3;
    const int wm = (w >> 1) * 64, wn = (w & 1) * 64;
    const int n0 = blockIdx.x * 128, m0 = blockIdx.y * 128;
    const uint32_t sb = (uint32_t)__cvta_generic_to_shared(smf);

    float acc[4][8][4];
#pragma unroll
    for (int i = 0; i < 4; i++)
#pragma unroll
        for (int j = 0; j < 8; j++)
#pragma unroll
            for (int l = 0; l < 4; l++) acc[i][j][l] = 0.0f;

    const int arow = tid >> 2, ach = tid & 3;

    auto stage_copy = [&](int s, int t) {
        const int k0 = t * 16;
        const uint32_t abase = sb + (uint32_t)(s * KAN_STG) * 4;
#pragma unroll
        for (int i = 0; i < 4; i++) {
            int row = arow + i * 32;
            cp16(abase + (uint32_t)(row * 20 + ach * 4) * 4,
                 g_E + (size_t)(m0 + row) * KEXP + k0 + ach * 4);
        }
        const uint32_t bbase = abase + (uint32_t)KA_E * 4;
#pragma unroll
        for (int i = 0; i < 4; i++) {
            int row = arow + i * 32;
            cp16(bbase + (uint32_t)(row * 20 + ach * 4) * 4,
                 g_Wk + (size_t)(n0 + row) * KEXP + k0 + ach * 4);
        }
    };

    const int NT = KEXP / 16;   // 45
#pragma unroll
    for (int s = 0; s < 3; s++) { stage_copy(s, s); CP_COMMIT(); }

    for (int t = 0; t < NT; t++) {
        CP_WAIT2();
        __syncthreads();
        if (t + 3 < NT) stage_copy((t + 3) & 3, t + 3);
        CP_COMMIT();

        const float* Ac = smf + (t & 3) * KAN_STG;
        const float* Bc = smf + (t & 3) * KAN_STG + KA_E;
#pragma unroll
        for (int ks = 0; ks < 2; ks++) {
            const int kc = ks * 8 + c;
            unsigned a[4][4], b[8][2];
#pragma unroll
            for (int mt = 0; mt < 4; mt++) {
                const float* p0 = Ac + (wm + mt * 16 + g) * 20;
                const float* p1 = p0 + 8 * 20;
                a[mt][0] = __float_as_uint(p0[kc]);
                a[mt][1] = __float_as_uint(p1[kc]);
                a[mt][2] = __float_as_uint(p0[kc + 4]);
                a[mt][3] = __float_as_uint(p1[kc + 4]);
            }
#pragma unroll
            for (int nt = 0; nt < 8; nt++) {
                const float* q = Bc + (wn + nt * 8 + g) * 20;
                b[nt][0] = __float_as_uint(q[kc]);
                b[nt][1] = __float_as_uint(q[kc + 4]);
            }
#pragma unroll
            for (int nt = 0; nt < 8; nt++)
#pragma unroll
                for (int mt = 0; mt < 4; mt++)
                    MMAT(acc[mt][nt], a[mt], b[nt]);
        }
    }

    // epilogue: all columns valid (o <= 255 < 257)
#pragma unroll
    for (int mt = 0; mt < 4; mt++) {
        int r0 = m0 + wm + mt * 16 + g, r1 = r0 + 8;
#pragma unroll
        for (int nt = 0; nt < 8; nt++) {
            int o = n0 + wn + nt * 8 + 2 * c;
            float* C = acc[mt][nt];
            float s0 = __ldg(&slope[o]), s1 = __ldg(&slope[o + 1]);
            out[(size_t)r0 * OUTS + o]     = 1.2f * sigf(s0 * C[0]);
            out[(size_t)r0 * OUTS + o + 1] = 1.2f * sigf(s1 * C[1]);
            out[(size_t)r1 * OUTS + o]     = 1.2f * sigf(s0 * C[2]);
            out[(size_t)r1 * OUTS + o + 1] = 1.2f * sigf(s1 * C[3]);
        }
    }
}

// ---------------------------------------------------------------------------
extern "C" void kernel_launch(void* const* d_in, const int* in_sizes, int n_in,
                              void* d_out, int out_size) {
    const float* x      = (const float*)d_in[0];
    const float* Wih_f  = (const float*)d_in[1];
    const float* Whh_f  = (const float*)d_in[2];
    const float* bih_f  = (const float*)d_in[3];
    const float* bhh_f  = (const float*)d_in[4];
    const float* Wih_b  = (const float*)d_in[5];
    const float* Whh_b  = (const float*)d_in[6];
    const float* bih_b  = (const float*)d_in[7];
    const float* bhh_b  = (const float*)d_in[8];
    const float* base_w = (const float*)d_in[9];
    const float* spl_w  = (const float*)d_in[10];
    const float* scaler = (const float*)d_in[11];
    const float* slope  = (const float*)d_in[12];
    float* out = (float*)d_out;

    cudaFuncSetAttribute(gemm_gi_kernel,  cudaFuncAttributeMaxDynamicSharedMemorySize, SMEM_BYTES);
    cudaFuncSetAttribute(gemm_kan_kernel, cudaFuncAttributeMaxDynamicSharedMemorySize, SMEM_BYTES);

    prep_xe_kernel<<<(NROWS * 68 + 255) / 256, 256>>>(x);
    prep_wg_kernel<<<(NGP * KP + 255) / 256, 256>>>(Wih_f, Wih_b);
    prep_wk_kernel<<<(OUTS * KEXP + 255) / 256, 256>>>(base_w, spl_w, scaler);

    gemm_gi_kernel<<<dim3(NGP / 128, NROWS / 128), 128, SMEM_BYTES>>>();
    feat_kernel<<<NROWS / 16, 256>>>(bih_f, bhh_f, bih_b, bhh_b, Whh_f, Whh_b, slope, out);
    gemm_kan_kernel<<<dim3(OUTN / 128, NROWS / 128), 128, SMEM_BYTES>>>(slope, out);
}

// round 17
// speedup vs baseline: 1.0072x; 1.0072x over previous
#include <cuda_runtime.h>
#include <cuda_bf16.h>
#include <cstdint>

// Problem constants
#define NROWS   64000      // B*T
#define TT      1000
#define INS     257
#define KP      272        // padded K for gate GEMM
#define XSTR    544        // Xe row stride in bf16: [hi 272 | lo 272]
#define HID     40
#define NGATE   480
#define NGP     512        // padded N for gate GEMM
#define KEXP    720
#define OUTS    257
#define OUTN    256        // KAN GEMM cols 0..255; col 256 fused into feat

// gi smem: per stage A 128x40 bf16 (10240B) + B 64x40 bf16 (5120B)
#define GI_STG_B  15360
// kan smem: per stage A 128x20 f32 (10240B) + B 64x20 f32 (5120B)
#define KAN_A_B   10240
#define KAN_STG_B 15360
#define SMEM_B    46080    // 3 stages

// Static device scratch
__device__ __nv_bfloat16 g_Xe[(size_t)NROWS * XSTR];
__device__ __nv_bfloat16 g_Wg[(size_t)NGP * XSTR];
__device__ float g_gi[(size_t)NROWS * NGATE];
__device__ float g_E [(size_t)NROWS * KEXP];
__device__ float g_Wk[(size_t)OUTS * KEXP];

__device__ __forceinline__ float sigf(float x) { return 1.0f / (1.0f + __expf(-x)); }
__device__ __forceinline__ unsigned tf32u(float v) {
    unsigned u; asm("cvt.rna.tf32.f32 %0, %1;" : "=r"(u) : "f"(v)); return u;
}
__device__ __forceinline__ float tf32f(float v) { return __uint_as_float(tf32u(v)); }

__device__ __forceinline__ void cp16(uint32_t dst, const void* src) {
    asm volatile("cp.async.cg.shared.global [%0], [%1], 16;" :: "r"(dst), "l"(src));
}
#define CP_COMMIT() asm volatile("cp.async.commit_group;")
#define CP_WAIT1()  asm volatile("cp.async.wait_group 1;")

#define LDSM4(R, addr) \
    asm volatile("ldmatrix.sync.aligned.m8n8.x4.shared.b16 {%0,%1,%2,%3}, [%4];" \
        : "=r"((R)[0]), "=r"((R)[1]), "=r"((R)[2]), "=r"((R)[3]) : "r"(addr))

#define MMAT(C, A, B) \
    asm volatile("mma.sync.aligned.m16n8k8.row.col.f32.tf32.tf32.f32 " \
        "{%0,%1,%2,%3},{%4,%5,%6,%7},{%8,%9},{%0,%1,%2,%3};" \
        : "+f"(C[0]), "+f"(C[1]), "+f"(C[2]), "+f"(C[3]) \
        : "r"(A[0]), "r"(A[1]), "r"(A[2]), "r"(A[3]), "r"(B[0]), "r"(B[1]))

#define MMAB(C, A, B) \
    asm volatile("mma.sync.aligned.m16n8k16.row.col.f32.bf16.bf16.f32 " \
        "{%0,%1,%2,%3},{%4,%5,%6,%7},{%8,%9},{%0,%1,%2,%3};" \
        : "+f"(C[0]), "+f"(C[1]), "+f"(C[2]), "+f"(C[3]) \
        : "r"(A[0]), "r"(A[1]), "r"(A[2]), "r"(A[3]), "r"(B[0]), "r"(B[1]))

// Cubic B-spline basis: grid[j] = 0.4*(j-3) - 1
__device__ __forceinline__ void bspline8(float x, float* o) {
    float bb[11];
#pragma unroll
    for (int j = 0; j < 11; j++) {
        float gA = 0.4f * (float)(j - 3) - 1.0f;
        float gB = 0.4f * (float)(j - 2) - 1.0f;
        bb[j] = (x >= gA && x < gB) ? 1.0f : 0.0f;
    }
#pragma unroll
    for (int k = 1; k <= 3; k++) {
        float inv = 1.0f / (0.4f * (float)k);
#pragma unroll
        for (int j = 0; j <= 10 - k; j++) {
            float gj = 0.4f * (float)(j - 3) - 1.0f;
            float gk = 0.4f * (float)(j + k - 2) - 1.0f;
            bb[j] = ((x - gj) * bb[j] + (gk - x) * bb[j + 1]) * inv;
        }
    }
#pragma unroll
    for (int m = 0; m < 8; m++) o[m] = bb[m];
}

// ---------------------------------------------------------------------------
// Prep kernels
// ---------------------------------------------------------------------------
__global__ void prep_xe_kernel(const float* __restrict__ X) {
    int idx = blockIdx.x * 256 + threadIdx.x;
    if (idx >= NROWS * 68) return;
    int m = idx / 68, kp = (idx % 68) * 4;
    union { __nv_bfloat16 b[4]; uint2 u; } H, L;
#pragma unroll
    for (int j = 0; j < 4; j++) {
        int k = kp + j;
        float v = (k < INS) ? X[(size_t)m * INS + k] : 0.0f;
        __nv_bfloat16 hi = __float2bfloat16_rn(v);
        H.b[j] = hi;
        L.b[j] = __float2bfloat16_rn(v - __bfloat162float(hi));
    }
    *(uint2*)(g_Xe + (size_t)m * XSTR + kp)       = H.u;
    *(uint2*)(g_Xe + (size_t)m * XSTR + 272 + kp) = L.u;
}

__global__ void prep_wg_kernel(const float* __restrict__ Wf,
                               const float* __restrict__ Wb) {
    int idx = blockIdx.x * 256 + threadIdx.x;
    if (idx >= NGP * KP) return;
    int g = idx / KP, k = idx % KP;
    float v = 0.0f;
    if (g < NGATE && k < INS)
        v = (g < 240) ? Wf[(size_t)g * INS + k] : Wb[(size_t)(g - 240) * INS + k];
    __nv_bfloat16 hi = __float2bfloat16_rn(v);
    g_Wg[(size_t)g * XSTR + k]       = hi;
    g_Wg[(size_t)g * XSTR + 272 + k] = __float2bfloat16_rn(v - __bfloat162float(hi));
}

__global__ void prep_wk_kernel(const float* __restrict__ base_w,
                               const float* __restrict__ spl_w,
                               const float* __restrict__ scaler) {
    int idx = blockIdx.x * 256 + threadIdx.x;
    if (idx >= OUTS * KEXP) return;
    int o = idx / KEXP, k = idx % KEXP;
    float v;
    if (k < 80) v = base_w[o * 80 + k];
    else {
        int q = k - 80;
        int i = q >> 3, m = q & 7;
        v = spl_w[(o * 80 + i) * 8 + m] * scaler[o * 80 + i];
    }
    g_Wk[idx] = tf32f(v);
}

// ---------------------------------------------------------------------------
// Kernel 1: gi = X * Wcat^T (bf16 3-term, 128x64 CTA, 4 warps, ldmatrix, 4 CTA/SM)
// ---------------------------------------------------------------------------
__global__ __launch_bounds__(128, 4)
void gemm_gi_kernel() {
    extern __shared__ __nv_bfloat16 smb[];
    const int tid = threadIdx.x, lane = tid & 31, w = tid >> 5;
    const int g = lane >> 2, c = lane & 3;
    const int wm = (w >> 1) * 64, wn = (w & 1) * 32;
    const int n0 = blockIdx.x * 64, m0 = blockIdx.y * 128;
    const uint32_t sb = (uint32_t)__cvta_generic_to_shared(smb);

    float acc[4][4][4];
#pragma unroll
    for (int i = 0; i < 4; i++)
#pragma unroll
        for (int j = 0; j < 4; j++)
#pragma unroll
            for (int l = 0; l < 4; l++) acc[i][j][l] = 0.0f;

    // ldmatrix lane-address offsets (80B row stride), relative to tile base
    // A: lanes 0-15 rows (wm + lane), k0 half; lanes 16-31 same rows, +16B (k8-15)
    const uint32_t aOff = (uint32_t)((wm + (lane & 15)) * 80 + (lane >> 4) * 16);
    // B x4: l0-7 -> rows wn+l,   +0  (nt pair lo, b0)
    //       l8-15 -> rows wn+l-8, +16 (b1)
    //       l16-23 -> rows wn+8+l-16, +0  (next nt, b0)
    //       l24-31 -> rows wn+8+l-24, +16 (b1)
    const uint32_t bOff = (uint32_t)((wn + ((lane >> 4) & 1) * 8 + (lane & 7)) * 80
                                     + ((lane >> 3) & 1) * 16);

    // stage copy: 768 cp16 over 128 threads (6 each)
    auto stage_copy = [&](int s, int t) {
        const int k0 = t * 16;
        const uint32_t st = sb + (uint32_t)(s * GI_STG_B);
#pragma unroll
        for (int i = 0; i < 6; i++) {
            int idx = tid + i * 128;
            int ch = idx & 3, r = idx >> 2;
            int ksrc = (ch < 2) ? (k0 + ch * 8) : (272 + k0 + (ch - 2) * 8);
            if (r < 128) {
                cp16(st + (uint32_t)(r * 80 + ch * 16),
                     g_Xe + (size_t)(m0 + r) * XSTR + ksrc);
            } else {
                int rb = r - 128;
                cp16(st + 10240u + (uint32_t)(rb * 80 + ch * 16),
                     g_Wg + (size_t)(n0 + rb) * XSTR + ksrc);
            }
        }
    };

    const int NT = KP / 16;   // 17
    stage_copy(0, 0); CP_COMMIT();
    stage_copy(1, 1); CP_COMMIT();

    for (int t = 0; t < NT; t++) {
        CP_WAIT1();
        __syncthreads();
        if (t + 2 < NT) stage_copy((t + 2) % 3, t + 2);
        CP_COMMIT();

        const uint32_t st = sb + (uint32_t)((t % 3) * GI_STG_B);
        const uint32_t aBase = st + aOff;
        const uint32_t bBase = st + 10240u + bOff;

        unsigned bh[8], bl[8], Af[4][4];
        LDSM4(bh,     bBase);                 // nt0 {b0,b1}, nt1 {b0,b1} hi
        LDSM4(bh + 4, bBase + 1280u);         // nt2, nt3 hi (+16 rows * 80B)
        LDSM4(bl,     bBase + 32u);           // lo plane (+32B)
        LDSM4(bl + 4, bBase + 1280u + 32u);
#pragma unroll
        for (int mt = 0; mt < 4; mt++) LDSM4(Af[mt], aBase + (uint32_t)(mt * 1280));
        // term 1: Ah * Bh
#pragma unroll
        for (int nt = 0; nt < 4; nt++)
#pragma unroll
            for (int mt = 0; mt < 4; mt++)
                MMAB(acc[mt][nt], Af[mt], (bh + 2 * nt));
        // term 2: Ah * Bl
#pragma unroll
        for (int nt = 0; nt < 4; nt++)
#pragma unroll
            for (int mt = 0; mt < 4; mt++)
                MMAB(acc[mt][nt], Af[mt], (bl + 2 * nt));
        // term 3: Al * Bh (reload A buffer with lo plane)
#pragma unroll
        for (int mt = 0; mt < 4; mt++) LDSM4(Af[mt], aBase + (uint32_t)(mt * 1280) + 32u);
#pragma unroll
        for (int nt = 0; nt < 4; nt++)
#pragma unroll
            for (int mt = 0; mt < 4; mt++)
                MMAB(acc[mt][nt], Af[mt], (bh + 2 * nt));
    }

#pragma unroll
    for (int mt = 0; mt < 4; mt++) {
        int r0 = m0 + wm + mt * 16 + g, r1 = r0 + 8;
#pragma unroll
        for (int nt = 0; nt < 4; nt++) {
            int o = n0 + wn + nt * 8 + 2 * c;
            if (o < NGATE) {
                float* C = acc[mt][nt];
                *(float2*)&g_gi[(size_t)r0 * NGATE + o] = make_float2(C[0], C[1]);
                *(float2*)&g_gi[(size_t)r1 * NGATE + o] = make_float2(C[2], C[3]);
            }
        }
    }
}

// ---------------------------------------------------------------------------
// Kernel 2: GRU cells + feature expansion + fused output column 256
// ---------------------------------------------------------------------------
__global__ __launch_bounds__(256)
void feat_kernel(const float* __restrict__ bih_f, const float* __restrict__ bhh_f,
                 const float* __restrict__ bih_b, const float* __restrict__ bhh_b,
                 const float* __restrict__ Whh_f, const float* __restrict__ Whh_b,
                 const float* __restrict__ slope, float* __restrict__ out) {
    __shared__ float sWf[40 * 120];
    __shared__ float sWb[40 * 120];
    __shared__ float sW256[KEXP];
    __shared__ float sh1f[4][40];
    __shared__ float sh1b[4][40];
    __shared__ float sred[4][2];

    const int tid = threadIdx.x, lane = tid & 31;
    for (int e = tid; e < 4800; e += 256) {
        int g = e / 40, j = e % 40;
        sWf[j * 120 + g] = Whh_f[4800 + e];
        sWb[j * 120 + g] = Whh_b[4800 + e];
    }
    for (int e = tid; e < KEXP; e += 256) sW256[e] = g_Wk[(size_t)256 * KEXP + e];
    __syncthreads();

    const int rl = tid >> 6;
    const int u  = tid & 63;
    const bool act = (u < HID);
    const float s256 = slope[256];

    float bf_r0=0, bf_z0=0, bf_n0=0, bb_r0=0, bb_z0=0, bb_n0=0;
    float if_r0=0, if_z0=0, if_n0=0, ib_r0=0, ib_z0=0, ib_n0=0;
    float bf_r1=0, bf_z1=0, bf_n1=0, bb_r1=0, bb_z1=0, bb_n1=0;
    float if_r1=0, if_z1=0, if_n1=0, ib_r1=0, ib_z1=0, ib_n1=0;
    if (act) {
        bf_r0 = bhh_f[u]; bf_z0 = bhh_f[40+u]; bf_n0 = bhh_f[80+u];
        bb_r0 = bhh_b[u]; bb_z0 = bhh_b[40+u]; bb_n0 = bhh_b[80+u];
        if_r0 = bih_f[u]; if_z0 = bih_f[40+u]; if_n0 = bih_f[80+u];
        ib_r0 = bih_b[u]; ib_z0 = bih_b[40+u]; ib_n0 = bih_b[80+u];
        bf_r1 = bhh_f[120+u]; bf_z1 = bhh_f[160+u]; bf_n1 = bhh_f[200+u];
        bb_r1 = bhh_b[120+u]; bb_z1 = bhh_b[160+u]; bb_n1 = bhh_b[200+u];
        if_r1 = bih_f[120+u]; if_z1 = bih_f[160+u]; if_n1 = bih_f[200+u];
        ib_r1 = bih_b[120+u]; ib_z1 = bih_b[160+u]; ib_n1 = bih_b[200+u];
    }

    for (int it = 0; it < 4; it++) {
        const int row = blockIdx.x * 16 + it * 4 + rl;
        const int b = row / TT, t = row % TT;
        const int row_rev = b * TT + (TT - 1 - t);
        const float* gf = g_gi + (size_t)row * NGATE;
        const float* gb = g_gi + (size_t)row_rev * NGATE;

        float h1f = 0.0f, h1b = 0.0f;
        if (act) {
            {
                float r = sigf(gf[u] + if_r0 + bf_r0);
                float z = sigf(gf[40 + u] + if_z0 + bf_z0);
                float n = tanhf(gf[80 + u] + if_n0 + r * bf_n0);
                h1f = (1.0f - z) * n;
                sh1f[rl][u] = h1f;
            }
            {
                float r = sigf(gb[240 + u] + ib_r0 + bb_r0);
                float z = sigf(gb[280 + u] + ib_z0 + bb_z0);
                float n = tanhf(gb[320 + u] + ib_n0 + r * bb_n0);
                h1b = (1.0f - z) * n;
                sh1b[rl][u] = h1b;
            }
        }
        __syncthreads();

        float part = 0.0f;
        if (act) {
            float gr = bf_r1, gz = bf_z1, gn = bf_n1;
#pragma unroll
            for (int j = 0; j < 40; j++) {
                float h = sh1f[rl][j];
                gr = fmaf(sWf[j * 120 + u],      h, gr);
                gz = fmaf(sWf[j * 120 + 40 + u], h, gz);
                gn = fmaf(sWf[j * 120 + 80 + u], h, gn);
            }
            float r = sigf(gf[120 + u] + if_r1 + gr);
            float z = sigf(gf[160 + u] + if_z1 + gz);
            float n = tanhf(gf[200 + u] + if_n1 + r * gn);
            float hf = (1.0f - z) * n + z * h1f;

            float br = bb_r1, bz = bb_z1, bn = bb_n1;
#pragma unroll
            for (int j = 0; j < 40; j++) {
                float h = sh1b[rl][j];
                br = fmaf(sWb[j * 120 + u],      h, br);
                bz = fmaf(sWb[j * 120 + 40 + u], h, bz);
                bn = fmaf(sWb[j * 120 + 80 + u], h, bn);
            }
            float r2 = sigf(gb[360 + u] + ib_r1 + br);
            float z2 = sigf(gb[400 + u] + ib_z1 + bz);
            float n2 = tanhf(gb[440 + u] + ib_n1 + r2 * bn);
            float hb = (1.0f - z2) * n2 + z2 * h1b;

            float* e = g_E + (size_t)row * KEXP;
            float e0 = tf32f(hf * sigf(hf));
            float e1 = tf32f(hb * sigf(hb));
            e[u]      = e0;
            e[40 + u] = e1;
            part = sW256[u] * e0 + sW256[40 + u] * e1;

            float bf[8], rv[8];
            bspline8(hf, bf);
#pragma unroll
            for (int j = 0; j < 8; j++) { rv[j] = tf32f(bf[j]); part = fmaf(sW256[80 + u * 8 + j], rv[j], part); }
            *(float4*)&e[80 + u * 8]     = make_float4(rv[0], rv[1], rv[2], rv[3]);
            *(float4*)&e[80 + u * 8 + 4] = make_float4(rv[4], rv[5], rv[6], rv[7]);

            bspline8(hb, bf);
#pragma unroll
            for (int j = 0; j < 8; j++) { rv[j] = tf32f(bf[j]); part = fmaf(sW256[80 + (40 + u) * 8 + j], rv[j], part); }
            *(float4*)&e[80 + (40 + u) * 8]     = make_float4(rv[0], rv[1], rv[2], rv[3]);
            *(float4*)&e[80 + (40 + u) * 8 + 4] = make_float4(rv[4], rv[5], rv[6], rv[7]);
        }

        float tot = part;
#pragma unroll
        for (int off = 16; off; off >>= 1) tot += __shfl_xor_sync(0xffffffffu, tot, off);
        if (lane == 0) sred[rl][(tid >> 5) & 1] = tot;
        __syncthreads();
        if (u == 0)
            out[(size_t)row * OUTS + 256] = 1.2f * sigf(s256 * (sred[rl][0] + sred[rl][1]));
    }
}

// ---------------------------------------------------------------------------
// Kernel 3: out[:,0:256] (tf32, 128x64 CTA, 4 warps, 4 CTA/SM)
// ---------------------------------------------------------------------------
__global__ __launch_bounds__(128, 4)
void gemm_kan_kernel(const float* __restrict__ slope, float* __restrict__ out) {
    extern __shared__ float smf[];
    const int tid = threadIdx.x, lane = tid & 31, w = tid >> 5;
    const int g = lane >> 2, c = lane & 3;
    const int wm = (w >> 1) * 64, wn = (w & 1) * 32;
    const int n0 = blockIdx.x * 64, m0 = blockIdx.y * 128;
    const uint32_t sb = (uint32_t)__cvta_generic_to_shared(smf);

    float acc[4][4][4];
#pragma unroll
    for (int i = 0; i < 4; i++)
#pragma unroll
        for (int j = 0; j < 4; j++)
#pragma unroll
            for (int l = 0; l < 4; l++) acc[i][j][l] = 0.0f;

    auto stage_copy = [&](int s, int t) {
        const int k0 = t * 16;
        const uint32_t st = sb + (uint32_t)(s * KAN_STG_B);
#pragma unroll
        for (int i = 0; i < 6; i++) {
            int idx = tid + i * 128;
            int ch = idx & 3, r = idx >> 2;
            if (r < 128) {
                cp16(st + (uint32_t)(r * 80 + ch * 16),
                     g_E + (size_t)(m0 + r) * KEXP + k0 + ch * 4);
            } else {
                int rb = r - 128;
                cp16(st + (uint32_t)KAN_A_B + (uint32_t)(rb * 80 + ch * 16),
                     g_Wk + (size_t)(n0 + rb) * KEXP + k0 + ch * 4);
            }
        }
    };

    const int NT = KEXP / 16;   // 45
    stage_copy(0, 0); CP_COMMIT();
    stage_copy(1, 1); CP_COMMIT();

    for (int t = 0; t < NT; t++) {
        CP_WAIT1();
        __syncthreads();
        if (t + 2 < NT) stage_copy((t + 2) % 3, t + 2);
        CP_COMMIT();

        const float* Ac = smf + (t % 3) * (KAN_STG_B / 4);
        const float* Bc = Ac + (KAN_A_B / 4);
#pragma unroll
        for (int ks = 0; ks < 2; ks++) {
            const int kc = ks * 8 + c;
            unsigned a[4][4], b[4][2];
#pragma unroll
            for (int mt = 0; mt < 4; mt++) {
                const float* p0 = Ac + (wm + mt * 16 + g) * 20;
                const float* p1 = p0 + 8 * 20;
                a[mt][0] = __float_as_uint(p0[kc]);
                a[mt][1] = __float_as_uint(p1[kc]);
                a[mt][2] = __float_as_uint(p0[kc + 4]);
                a[mt][3] = __float_as_uint(p1[kc + 4]);
            }
#pragma unroll
            for (int nt = 0; nt < 4; nt++) {
                const float* q = Bc + (wn + nt * 8 + g) * 20;
                b[nt][0] = __float_as_uint(q[kc]);
                b[nt][1] = __float_as_uint(q[kc + 4]);
            }
#pragma unroll
            for (int nt = 0; nt < 4; nt++)
#pragma unroll
                for (int mt = 0; mt < 4; mt++)
                    MMAT(acc[mt][nt], a[mt], b[nt]);
        }
    }

#pragma unroll
    for (int mt = 0; mt < 4; mt++) {
        int r0 = m0 + wm + mt * 16 + g, r1 = r0 + 8;
#pragma unroll
        for (int nt = 0; nt < 4; nt++) {
            int o = n0 + wn + nt * 8 + 2 * c;
            float* C = acc[mt][nt];
            float s0 = __ldg(&slope[o]), s1 = __ldg(&slope[o + 1]);
            out[(size_t)r0 * OUTS + o]     = 1.2f * sigf(s0 * C[0]);
            out[(size_t)r0 * OUTS + o + 1] = 1.2f * sigf(s1 * C[1]);
            out[(size_t)r1 * OUTS + o]     = 1.2f * sigf(s0 * C[2]);
            out[(size_t)r1 * OUTS + o + 1] = 1.2f * sigf(s1 * C[3]);
        }
    }
}

// ---------------------------------------------------------------------------
extern "C" void kernel_launch(void* const* d_in, const int* in_sizes, int n_in,
                              void* d_out, int out_size) {
    const float* x      = (const float*)d_in[0];
    const float* Wih_f  = (const float*)d_in[1];
    const float* Whh_f  = (const float*)d_in[2];
    const float* bih_f  = (const float*)d_in[3];
    const float* bhh_f  = (const float*)d_in[4];
    const float* Wih_b  = (const float*)d_in[5];
    const float* Whh_b  = (const float*)d_in[6];
    const float* bih_b  = (const float*)d_in[7];
    const float* bhh_b  = (const float*)d_in[8];
    const float* base_w = (const float*)d_in[9];
    const float* spl_w  = (const float*)d_in[10];
    const float* scaler = (const float*)d_in[11];
    const float* slope  = (const float*)d_in[12];
    float* out = (float*)d_out;

    prep_xe_kernel<<<(NROWS * 68 + 255) / 256, 256>>>(x);
    prep_wg_kernel<<<(NGP * KP + 255) / 256, 256>>>(Wih_f, Wih_b);
    prep_wk_kernel<<<(OUTS * KEXP + 255) / 256, 256>>>(base_w, spl_w, scaler);

    gemm_gi_kernel<<<dim3(NGP / 64, NROWS / 128), 128, SMEM_B>>>();
    feat_kernel<<<NROWS / 16, 256>>>(bih_f, bhh_f, bih_b, bhh_b, Whh_f, Whh_b, slope, out);
    gemm_kan_kernel<<<dim3(OUTN / 64, NROWS / 128), 128, SMEM_B>>>(slope, out);
}